// round 4
// baseline (speedup 1.0000x reference)
#include <cuda_runtime.h>

// Fixed problem shapes
#define BB   32
#define CC_  512
#define HH   56
#define WW   56
#define HW   (HH*WW)          // 3136
#define NCL  27
#define NPIX (BB*HW)          // 100352

#define CH    32              // channels per smem tile
#define PXB   64              // pixels per block (3136/64 = 49 blocks per image)
#define BLKS  (NPIX/PXB)      // 1568
#define NTHR  96              // 3 warps: one 9-cluster group per warp

typedef unsigned long long ull;

// Normalized clusters, duplicated into both halves of an f32x2 lane:
// g_cl2[n*C + c] = pack(v, v),  v = clusters[n][c] / ||clusters[n]||
__device__ ull g_cl2[NCL * CC_];

__device__ __forceinline__ ull fma2(ull a, ull b, ull c) {
    ull d;
    asm("fma.rn.f32x2 %0, %1, %2, %3;" : "=l"(d) : "l"(a), "l"(b), "l"(c));
    return d;
}
__device__ __forceinline__ ull pack2(float lo, float hi) {
    float2 t = make_float2(lo, hi);
    return *reinterpret_cast<ull*>(&t);
}

// One block (32 threads) per cluster row: L2-normalize + duplicate-pack.
// Block 0 lane 0 also zeroes the loss accumulator.
__global__ void prep_kernel(const float* __restrict__ cl, float* __restrict__ out) {
    int n = blockIdx.x;
    int lane = threadIdx.x;
    if (n == 0 && lane == 0) out[0] = 0.0f;
    float s = 0.f;
    #pragma unroll
    for (int c = lane; c < CC_; c += 32) {
        float v = cl[n * CC_ + c];
        s += v * v;
    }
    #pragma unroll
    for (int o = 16; o > 0; o >>= 1) s += __shfl_xor_sync(0xffffffffu, s, o);
    float inv = 1.0f / fmaxf(sqrtf(s), 1e-12f);
    #pragma unroll
    for (int c = lane; c < CC_; c += 32)
        g_cl2[n * CC_ + c] = pack2(cl[n * CC_ + c] * inv, cl[n * CC_ + c] * inv);
}

// Main kernel: 3 warps (9 clusters each) share a 64-pixel x tile in smem.
// lane = pixel-pair index (32 pairs = 64 px). f32x2 math throughout.
__global__ __launch_bounds__(NTHR)
void cluster_main_kernel(const float* __restrict__ x, float* __restrict__ out) {
    // xs: [CH/2][32 pairs][2 ch] = 1024 ull (8KB), cls: [27][CH] = 864 ull
    __shared__ __align__(16) ull sm[1024 + NCL * CH];
    ull* xs  = sm;
    ull* cls = sm + 1024;

    const int tid  = threadIdx.x;
    const int warp = tid >> 5;
    const int lane = tid & 31;
    const int g9   = warp * 9;

    const int blk = blockIdx.x;
    const int b   = blk / 49;
    const int px0 = (blk - b * 49) * PXB;
    const float* xb = x + (size_t)b * CC_ * HW + px0;

    ull acc[9];
    #pragma unroll
    for (int n = 0; n < 9; n++) acc[n] = 0ull;
    ull nrm = 0ull;

    for (int c0 = 0; c0 < CC_; c0 += CH) {
        __syncthreads();
        // stage x tile: CH rows of 64 contiguous floats -> interleaved pairs
        // xs layout: [c2][pair][k] linear = c2*64 + pair*2 + k, k = c&1
        for (int t = tid; t < CH * 16; t += NTHR) {
            int c = t >> 4, j = t & 15;               // j-th float4 of row c
            float4 v = *reinterpret_cast<const float4*>(
                xb + (size_t)(c0 + c) * HW + 4 * j);
            int base = (c >> 1) * 64 + (c & 1);
            xs[base + 4 * j]     = pack2(v.x, v.y);   // pair 2j
            xs[base + 4 * j + 2] = pack2(v.z, v.w);   // pair 2j+1
        }
        // stage cluster tile: cls[n][c'] = g_cl2[n*512 + c0 + c']
        for (int t = tid; t < NCL * CH / 2; t += NTHR) {
            reinterpret_cast<ulonglong2*>(cls)[t] =
                reinterpret_cast<const ulonglong2*>(g_cl2)
                    [(t >> 4) * (CC_ / 2) + (c0 >> 1) + (t & 15)];
        }
        __syncthreads();

        #pragma unroll
        for (int c2 = 0; c2 < CH / 2; c2++) {
            ulonglong2 xv = *reinterpret_cast<const ulonglong2*>(
                &xs[c2 * 64 + lane * 2]);             // 2 channels of this pair
            nrm = fma2(xv.x, xv.x, nrm);
            nrm = fma2(xv.y, xv.y, nrm);
            #pragma unroll
            for (int n = 0; n < 9; n++) {
                ulonglong2 w = *reinterpret_cast<const ulonglong2*>(
                    &cls[(g9 + n) * CH + 2 * c2]);    // broadcast LDS.128
                acc[n] = fma2(xv.x, w.x, acc[n]);
                acc[n] = fma2(xv.y, w.y, acc[n]);
            }
        }
    }

    // ---- epilogue: gather all 27 dots per pair, softmax, store, loss ----
    __syncthreads();
    ull* zs = sm;                                     // overlay dead x tile
    #pragma unroll
    for (int n = 0; n < 9; n++) zs[(g9 + n) * 32 + lane] = acc[n];
    __syncthreads();

    if (warp == 0) {
        float2 nf = *reinterpret_cast<float2*>(&nrm);
        float inv0 = 1.0f / fmaxf(sqrtf(nf.x), 1e-12f);
        float inv1 = 1.0f / fmaxf(sqrtf(nf.y), 1e-12f);

        float z0[NCL], z1[NCL];
        float m0 = -1e30f, m1 = -1e30f;
        #pragma unroll
        for (int n = 0; n < NCL; n++) {
            ull a = zs[n * 32 + lane];
            float2 d = *reinterpret_cast<float2*>(&a);
            z0[n] = 2.0f * d.x * inv0;                // alpha * inner
            z1[n] = 2.0f * d.y * inv1;
            m0 = fmaxf(m0, z0[n]);
            m1 = fmaxf(m1, z1[n]);
        }
        float s0 = 0.f, s1 = 0.f, l0 = 0.f, l1 = 0.f;
        #pragma unroll
        for (int n = 0; n < NCL; n++) {
            float e0 = __expf(z0[n] - m0);
            float e1 = __expf(z1[n] - m1);
            s0 += e0; s1 += e1;
            l0 += e0 * z0[n];
            l1 += e1 * z1[n];
            z0[n] = e0; z1[n] = e1;
        }
        float rs0 = 1.0f / s0, rs1 = 1.0f / s1;

        // probs start at out+1 -> 4B-aligned only: scalar stores.
        float* po = out + 1 + (size_t)b * NCL * HW + px0 + 2 * lane;
        #pragma unroll
        for (int n = 0; n < NCL; n++) {
            float* q = po + (size_t)n * HW;
            q[0] = z0[n] * rs0;
            q[1] = z1[n] * rs1;
        }

        // loss: sum_n prob*inner = (sum e*z)/(2*sum e); fold -1/NPIX here.
        float l = (l0 * rs0 + l1 * rs1) * (-0.5f / (float)NPIX);
        #pragma unroll
        for (int o = 16; o > 0; o >>= 1) l += __shfl_xor_sync(0xffffffffu, l, o);
        if (lane == 0) atomicAdd(out, l);
    }
}

extern "C" void kernel_launch(void* const* d_in, const int* in_sizes, int n_in,
                              void* d_out, int out_size) {
    const float* x  = (const float*)d_in[0];   // [32, 512, 56, 56]
    const float* cl = (const float*)d_in[1];   // [27, 512]
    float* out = (float*)d_out;                // [0]=loss, [1..]=probs

    prep_kernel<<<NCL, 32>>>(cl, out);
    cluster_main_kernel<<<BLKS, NTHR>>>(x, out);
}